// round 9
// baseline (speedup 1.0000x reference)
#include <cuda_runtime.h>
#include <cuda_bf16.h>
#include <math.h>
#include <stdint.h>

#define N_GENE  20000
#define N_TRAIN 4096
#define N_EDGES 131072
#define SRC     2500
#define DSTD    2675
#define HD      2500
#define OUTD    2500
#define NC      16
#define TRAINF  (DSTD - NC)   // 2659
#define EPS_F   1e-5f
#define SLOPE_F 0.01f

// padded K dims (multiple of 32 BEFORE the 3-slot interleave)
#define KP_DST  2688
#define KP_HD   2560
#define KP_S    4096
#define NP_HD   2560   // 20 col tiles
#define NP_QKV  7680   // 60 col tiles
#define NP_S    4096   // 32 col tiles

// ---------------- fp32 scratch ----------------------------------------------
__device__ float g_dst [(size_t)N_TRAIN * DSTD];
__device__ float g_agg [(size_t)N_TRAIN * SRC];
__device__ float g_deg [N_TRAIN];
__device__ float g_h1  [(size_t)N_TRAIN * HD];
__device__ float g_qkv [(size_t)N_TRAIN * NP_QKV];   // [q | k | v] fused, 2560 cols each
__device__ float g_S   [(size_t)N_TRAIN * N_TRAIN];
__device__ float g_av  [(size_t)N_TRAIN * HD];
__device__ float g_h2  [(size_t)N_TRAIN * HD];
__device__ float g_h3  [(size_t)N_TRAIN * OUTD];
__device__ float g_t   [(size_t)N_TRAIN * OUTD];
__device__ float g_bias[NP_QKV];
__device__ float g_psum[32 * HD];
__device__ float g_psq [32 * HD];
__device__ float g_bna [HD];
__device__ float g_bnc [HD];

// ---------------- bf16 3-slot interleaved buffers ----------------------------
// A pattern per k: [ah, al, ah] ; B pattern per k: [bh, bh, bl]
// dot(A',B') = ah*bh + al*bh + ah*bl = (ah+al)(bh+bl) - al*bl  (residual ~2^-16)
__device__ __nv_bfloat16 g_A0[(size_t)4096 * 3 * 4096];
__device__ __nv_bfloat16 g_A1[(size_t)4096 * 3 * KP_HD];
__device__ __nv_bfloat16 g_B0[(size_t)NP_QKV * 3 * KP_HD];   // 118 MB (fused QKV worst case)

// =============================================================================
// PTX helpers (portable compute_80-level only — tcgen05 rejected by this
// harness's compute_103 ptxas target)
// =============================================================================
__device__ __forceinline__ uint32_t smem_to_u32(const void* p) {
    uint32_t a;
    asm("{ .reg .u64 t; cvta.to.shared.u64 t, %1; cvt.u32.u64 %0, t; }" : "=r"(a) : "l"(p));
    return a;
}
__device__ __forceinline__ void cp16(uint32_t s, const void* g) {
    asm volatile("cp.async.cg.shared.global [%0], [%1], 16;" :: "r"(s), "l"(g));
}
__device__ __forceinline__ void cp_commit() { asm volatile("cp.async.commit_group;" ::: "memory"); }
__device__ __forceinline__ void cp_wait2()  { asm volatile("cp.async.wait_group 2;" ::: "memory"); }

__device__ __forceinline__ void ldsm4(uint32_t* r, uint32_t addr) {
    asm volatile("ldmatrix.sync.aligned.m8n8.x4.shared.b16 {%0,%1,%2,%3}, [%4];"
                 : "=r"(r[0]), "=r"(r[1]), "=r"(r[2]), "=r"(r[3]) : "r"(addr));
}
__device__ __forceinline__ void mma_bf16(float* c, const uint32_t* a, uint32_t b0, uint32_t b1) {
    asm volatile(
        "mma.sync.aligned.m16n8k16.row.col.f32.bf16.bf16.f32 "
        "{%0,%1,%2,%3}, {%4,%5,%6,%7}, {%8,%9}, {%0,%1,%2,%3};\n"
        : "+f"(c[0]), "+f"(c[1]), "+f"(c[2]), "+f"(c[3])
        : "r"(a[0]), "r"(a[1]), "r"(a[2]), "r"(a[3]), "r"(b0), "r"(b1));
}
__device__ __forceinline__ uint32_t pack2(__nv_bfloat16 lo, __nv_bfloat16 hi) {
    uint16_t a = __bfloat16_as_ushort(lo), b = __bfloat16_as_ushort(hi);
    return (uint32_t)a | ((uint32_t)b << 16);
}

// =============================================================================
// small utility kernels
// =============================================================================
__global__ void k_zero(float* p, long n) {
    long i = (long)blockIdx.x * blockDim.x + threadIdx.x;
    if (i < n) p[i] = 0.0f;
}

__global__ void k_concat(const float* __restrict__ tf, const float* __restrict__ yh,
                         float* __restrict__ dst) {
    long i = (long)blockIdx.x * blockDim.x + threadIdx.x;
    long total = (long)N_TRAIN * DSTD;
    if (i >= total) return;
    int r = (int)(i / DSTD), c = (int)(i % DSTD);
    dst[i] = (c < TRAINF) ? tf[(long)r * TRAINF + c] : yh[(long)r * NC + (c - TRAINF)];
}

__global__ void k_cat_bias(const float* __restrict__ bq, const float* __restrict__ bk,
                           const float* __restrict__ bv, float* __restrict__ o) {
    int i = blockIdx.x * 256 + threadIdx.x;
    if (i >= NP_QKV) return;
    int seg = i / 2560, j = i % 2560;
    const float* b = (seg == 0) ? bq : (seg == 1 ? bk : bv);
    o[i] = (j < HD) ? b[j] : 0.0f;
}

__global__ void k_deg(const int* __restrict__ di, float* __restrict__ deg) {
    int e = blockIdx.x * blockDim.x + threadIdx.x;
    if (e < N_EDGES) atomicAdd(&deg[di[e]], 1.0f);
}

__global__ void k_scatter(const float* __restrict__ gene, const int* __restrict__ si,
                          const int* __restrict__ di, float* __restrict__ agg) {
    int e = blockIdx.x;
    int s = si[e], d = di[e];
    const float* g = gene + (long)s * SRC;
    float* a = agg + (long)d * SRC;
    for (int c = threadIdx.x; c < SRC; c += blockDim.x)
        atomicAdd(&a[c], g[c]);
}

__global__ void k_mean(float* __restrict__ agg, const float* __restrict__ deg) {
    long i = (long)blockIdx.x * blockDim.x + threadIdx.x;
    long total = (long)N_TRAIN * SRC;
    if (i >= total) return;
    int r = (int)(i / SRC);
    agg[i] *= 1.0f / fmaxf(deg[r], 1.0f);
}

// fp32 [M x K] (row stride ldin) -> bf16 [M x 3*Kp], per-k pattern [ah, al, ah]
__global__ void k_split_a3(const float* __restrict__ in, __nv_bfloat16* __restrict__ out,
                           int M, int K, int Kp, int ldin) {
    long i = (long)blockIdx.x * blockDim.x + threadIdx.x;
    long total = (long)M * (Kp >> 1);
    if (i >= total) return;
    int half = Kp >> 1;
    int r = (int)(i / half), p = (int)(i % half);
    int c0 = 2 * p;
    float v0 = (c0     < K) ? in[(long)r * ldin + c0]     : 0.0f;
    float v1 = (c0 + 1 < K) ? in[(long)r * ldin + c0 + 1] : 0.0f;
    __nv_bfloat16 h0 = __float2bfloat16(v0);
    __nv_bfloat16 l0 = __float2bfloat16(v0 - __bfloat162float(h0));
    __nv_bfloat16 h1 = __float2bfloat16(v1);
    __nv_bfloat16 l1 = __float2bfloat16(v1 - __bfloat162float(h1));
    uint32_t* o = (uint32_t*)(out + (long)r * 3 * Kp + 3 * c0);
    o[0] = pack2(h0, l0);
    o[1] = pack2(h0, h1);
    o[2] = pack2(l1, h1);
}

// fp32 [M x K] (row stride ldin) -> bf16 [M x 3*Kp], per-k pattern [bh, bh, bl]
__global__ void k_split_b3_rows(const float* __restrict__ in, __nv_bfloat16* __restrict__ out,
                                int M, int K, int Kp, int ldin) {
    long i = (long)blockIdx.x * blockDim.x + threadIdx.x;
    long total = (long)M * (Kp >> 1);
    if (i >= total) return;
    int half = Kp >> 1;
    int r = (int)(i / half), p = (int)(i % half);
    int c0 = 2 * p;
    float v0 = (c0     < K) ? in[(long)r * ldin + c0]     : 0.0f;
    float v1 = (c0 + 1 < K) ? in[(long)r * ldin + c0 + 1] : 0.0f;
    __nv_bfloat16 h0 = __float2bfloat16(v0);
    __nv_bfloat16 l0 = __float2bfloat16(v0 - __bfloat162float(h0));
    __nv_bfloat16 h1 = __float2bfloat16(v1);
    __nv_bfloat16 l1 = __float2bfloat16(v1 - __bfloat162float(h1));
    uint32_t* o = (uint32_t*)(out + (long)r * 3 * Kp + 3 * c0);
    o[0] = pack2(h0, h0);
    o[1] = pack2(l0, h1);
    o[2] = pack2(h1, l1);
}

// fp32 [K x N] (row stride ldin) -> transposed bf16 [Np x 3*Kp], pattern [bh, bh, bl]
__global__ void k_split_bt3(const float* __restrict__ in, __nv_bfloat16* __restrict__ out,
                            int K, int N, int Kp, int Np, int ldin) {
    __shared__ float t[32][33];
    int k0 = blockIdx.x * 32, n0 = blockIdx.y * 32;
    int x = threadIdx.x, y = threadIdx.y;   // 32 x 8
    for (int i = y; i < 32; i += 8) {
        int k = k0 + i, n = n0 + x;
        t[i][x] = (k < K && n < N) ? in[(long)k * ldin + n] : 0.0f;
    }
    __syncthreads();
    long K2 = 3L * Kp;
    for (int i = y; i < 32; i += 8) {
        int n = n0 + i, k = k0 + x;
        float v = t[x][i];
        __nv_bfloat16 h = __float2bfloat16(v);
        __nv_bfloat16 l = __float2bfloat16(v - __bfloat162float(h));
        __nv_bfloat16* o = out + (long)n * K2 + 3 * k;
        o[0] = h; o[1] = h; o[2] = l;
    }
}

// =============================================================================
// bf16 mma.sync GEMM: C[M x N] = act( alpha*(A@B^T) + bias + (acc?C:0) )
// CTA tile 256x128, BK=32, 4-stage cp.async, 8 warps (4m x 2n), warp 64x64
// smem row stride 80B (bank-conflict-free for cp.async 16B and ldmatrix)
// =============================================================================
#define STAGES 4
#define A_BYTES 20480                 // 256 rows * 80
#define B_BYTES 10240                 // 128 rows * 80
#define STAGE_BYTES (A_BYTES + B_BYTES)
#define GEMM_SMEM (STAGES * STAGE_BYTES)

__device__ __forceinline__ void g_load_stage(uint32_t sbase, int stage,
    const __nv_bfloat16* A, const __nv_bfloat16* B, int m0, int n0, long K2, int kb)
{
    uint32_t sA = sbase + stage * STAGE_BYTES;
    uint32_t sB = sA + A_BYTES;
    int tid = threadIdx.x;
    const char* Ab = (const char*)(A + (long)m0 * K2);
    const char* Bb = (const char*)(B + (long)n0 * K2);
    long kofs = (long)kb * 32;
    #pragma unroll
    for (int i = 0; i < 4; i++) {                 // A: 1024 cp16
        int idx = tid + i * 256;
        int r = idx >> 2, c = idx & 3;
        cp16(sA + r * 80 + c * 16, Ab + ((long)r * K2 + kofs + c * 8) * 2);
    }
    #pragma unroll
    for (int i = 0; i < 2; i++) {                 // B: 512 cp16
        int idx = tid + i * 256;
        int r = idx >> 2, c = idx & 3;
        cp16(sB + r * 80 + c * 16, Bb + ((long)r * K2 + kofs + c * 8) * 2);
    }
}

__global__ __launch_bounds__(256, 1)
void k_mma_gemm(const __nv_bfloat16* __restrict__ A, const __nv_bfloat16* __restrict__ B,
                float* __restrict__ C, int N, long K2,
                const float* __restrict__ bias, float alpha, int acc, int act) {
    extern __shared__ char smem[];
    uint32_t sbase = smem_to_u32(smem);
    int tid = threadIdx.x;
    int warp = tid >> 5, lane = tid & 31;
    int wm = warp & 3, wn = warp >> 2;            // 4 x 2 warp grid, warp tile 64x64
    int m0 = blockIdx.y * 256, n0 = blockIdx.x * 128;

    float accf[4][8][4];
    #pragma unroll
    for (int i = 0; i < 4; i++)
        #pragma unroll
        for (int j = 0; j < 8; j++)
            #pragma unroll
            for (int l = 0; l < 4; l++) accf[i][j][l] = 0.0f;

    const int nkb = (int)(K2 >> 5);

    #pragma unroll
    for (int s = 0; s < STAGES - 1; s++) {
        if (s < nkb) g_load_stage(sbase, s, A, B, m0, n0, K2, s);
        cp_commit();
    }

    int lrow = lane & 15;
    int lcol = (lane >> 4) * 16;

    for (int kb = 0; kb < nkb; kb++) {
        cp_wait2();
        __syncthreads();
        int stage = kb & (STAGES - 1);
        uint32_t sA = sbase + stage * STAGE_BYTES;
        uint32_t sB = sA + A_BYTES;

        #pragma unroll
        for (int kk = 0; kk < 2; kk++) {
            uint32_t a[4][4], bq[4][4];
            #pragma unroll
            for (int mi = 0; mi < 4; mi++)
                ldsm4(a[mi], sA + (wm * 64 + mi * 16 + lrow) * 80 + kk * 32 + lcol);
            #pragma unroll
            for (int nb = 0; nb < 4; nb++)
                ldsm4(bq[nb], sB + (wn * 64 + nb * 16 + lrow) * 80 + kk * 32 + lcol);
            #pragma unroll
            for (int mi = 0; mi < 4; mi++)
                #pragma unroll
                for (int nb = 0; nb < 4; nb++) {
                    mma_bf16(accf[mi][2 * nb],     a[mi], bq[nb][0], bq[nb][2]);
                    mma_bf16(accf[mi][2 * nb + 1], a[mi], bq[nb][1], bq[nb][3]);
                }
        }

        int nk = kb + STAGES - 1;
        if (nk < nkb) g_load_stage(sbase, nk & (STAGES - 1), A, B, m0, n0, K2, nk);
        cp_commit();
    }

    #pragma unroll
    for (int mi = 0; mi < 4; mi++) {
        int row0 = m0 + wm * 64 + mi * 16 + (lane >> 2);
        #pragma unroll
        for (int ni = 0; ni < 8; ni++) {
            int col = n0 + wn * 64 + ni * 8 + (lane & 3) * 2;
            if (col >= N) continue;
            float b0 = 0.f, b1 = 0.f;
            if (bias) { b0 = bias[col]; b1 = bias[col + 1]; }
            #pragma unroll
            for (int h = 0; h < 2; h++) {
                int row = row0 + h * 8;
                float v0 = accf[mi][ni][2 * h]     * alpha + b0;
                float v1 = accf[mi][ni][2 * h + 1] * alpha + b1;
                float* cp = &C[(long)row * N + col];
                if (acc) { float2 p = *(float2*)cp; v0 += p.x; v1 += p.y; }
                if (act) { v0 = fmaxf(v0, 0.f); v1 = fmaxf(v1, 0.f); }
                float2 o; o.x = v0; o.y = v1;
                *(float2*)cp = o;
            }
        }
    }
}

// =============================================================================
// softmax / BN / LN / head
// =============================================================================
__global__ void k_softmax(float* __restrict__ S, int n) {
    int r = blockIdx.x;
    float* row = S + (long)r * n;
    __shared__ float red[256];
    int tid = threadIdx.x;
    float mx = -INFINITY;
    for (int i = tid; i < n; i += 256) mx = fmaxf(mx, row[i]);
    red[tid] = mx; __syncthreads();
    for (int s = 128; s > 0; s >>= 1) {
        if (tid < s) red[tid] = fmaxf(red[tid], red[tid + s]);
        __syncthreads();
    }
    mx = red[0]; __syncthreads();
    float sum = 0.0f;
    for (int i = tid; i < n; i += 256) {
        float e = __expf(row[i] - mx);
        row[i] = e; sum += e;
    }
    red[tid] = sum; __syncthreads();
    for (int s = 128; s > 0; s >>= 1) {
        if (tid < s) red[tid] += red[tid + s];
        __syncthreads();
    }
    float inv = 1.0f / red[0];
    for (int i = tid; i < n; i += 256) row[i] *= inv;
}

__global__ void k_bn_partial(const float* __restrict__ X, int N) {
    int col = blockIdx.x * 256 + threadIdx.x;
    int rt = blockIdx.y;
    if (col >= N) return;
    const int RPT = N_TRAIN / 32;
    float s = 0.0f, q = 0.0f;
    int r0 = rt * RPT;
    for (int r = r0; r < r0 + RPT; r++) {
        float v = X[(long)r * N + col];
        s += v; q += v * v;
    }
    g_psum[rt * N + col] = s;
    g_psq [rt * N + col] = q;
}

__global__ void k_bn_final(const float* __restrict__ g, const float* __restrict__ b, int N) {
    int col = blockIdx.x * 256 + threadIdx.x;
    if (col >= N) return;
    float s = 0.0f, q = 0.0f;
    for (int t = 0; t < 32; t++) { s += g_psum[t * N + col]; q += g_psq[t * N + col]; }
    float m = s / (float)N_TRAIN;
    float var = q / (float)N_TRAIN - m * m;
    float sc = g[col] * rsqrtf(var + EPS_F);
    g_bna[col] = sc;
    g_bnc[col] = b[col] - m * sc;
}

__global__ void k_bn_apply(const float* __restrict__ X, float* __restrict__ Y, int N) {
    long i = (long)blockIdx.x * blockDim.x + threadIdx.x;
    long total = (long)N_TRAIN * N;
    if (i >= total) return;
    int col = (int)(i % N);
    float v = X[i] * g_bna[col] + g_bnc[col];
    Y[i] = (v >= 0.0f) ? v : SLOPE_F * v;
}

__global__ void k_ln_leaky(float* __restrict__ X, const float* __restrict__ g,
                           const float* __restrict__ b, int N) {
    int r = blockIdx.x;
    float* row = X + (long)r * N;
    __shared__ float r1[256], r2[256];
    int tid = threadIdx.x;
    float s = 0.0f, q = 0.0f;
    for (int i = tid; i < N; i += 256) { float v = row[i]; s += v; q += v * v; }
    r1[tid] = s; r2[tid] = q; __syncthreads();
    for (int st = 128; st > 0; st >>= 1) {
        if (tid < st) { r1[tid] += r1[tid + st]; r2[tid] += r2[tid + st]; }
        __syncthreads();
    }
    float m = r1[0] / (float)N;
    float var = r2[0] / (float)N - m * m;
    float inv = rsqrtf(var + EPS_F);
    for (int i = tid; i < N; i += 256) {
        float v = (row[i] - m) * inv * g[i] + b[i];
        row[i] = (v >= 0.0f) ? v : SLOPE_F * v;
    }
}

__global__ void k_out_gemm(const float* __restrict__ T, const float* __restrict__ W,
                           const float* __restrict__ bias, float* __restrict__ Y) {
    int r = blockIdx.x;
    int tid = threadIdx.x;
    int col = tid & 15, kg = tid >> 4;
    float acc = 0.0f;
    for (int k = kg; k < OUTD; k += 16)
        acc += T[(long)r * OUTD + k] * W[k * NC + col];
    __shared__ float red[256];
    red[tid] = acc; __syncthreads();
    if (kg == 0) {
        float s = 0.0f;
        for (int t = 0; t < 16; t++) s += red[col + 16 * t];
        Y[(long)r * NC + col] = s + bias[col];
    }
}

// =============================================================================
// launch
// =============================================================================
static inline int cdiv(long a, long b) { return (int)((a + b - 1) / b); }

extern "C" void kernel_launch(void* const* d_in, const int* in_sizes, int n_in,
                              void* d_out, int out_size) {
    const float* gene   = (const float*)d_in[0];
    const float* trainf = (const float*)d_in[1];
    const float* yhat   = (const float*)d_in[2];
    const int*   esrc   = (const int*)  d_in[3];
    const int*   edst   = (const int*)  d_in[4];
    const float* Wself3 = (const float*)d_in[5];
    const float* Wneigh3= (const float*)d_in[6];
    const float* b3     = (const float*)d_in[7];
    const float* bn3g   = (const float*)d_in[8];
    const float* bn3b   = (const float*)d_in[9];
    const float* Wq     = (const float*)d_in[10];
    const float* Wk     = (const float*)d_in[11];
    const float* Wv     = (const float*)d_in[12];
    const float* bq     = (const float*)d_in[13];
    const float* bk     = (const float*)d_in[14];
    const float* bv     = (const float*)d_in[15];
    const float* Wo     = (const float*)d_in[16];
    const float* bo     = (const float*)d_in[17];
    const float* ln2g   = (const float*)d_in[18];
    const float* ln2b   = (const float*)d_in[19];
    const float* Wself4 = (const float*)d_in[20];
    const float* Wneigh4= (const float*)d_in[21];
    const float* b4     = (const float*)d_in[22];
    const float* bn4g   = (const float*)d_in[23];
    const float* bn4b   = (const float*)d_in[24];
    const float* Wlin2  = (const float*)d_in[25];
    const float* blin2  = (const float*)d_in[26];
    const float* Wce    = (const float*)d_in[27];
    const float* bce    = (const float*)d_in[28];

    float* out_xhat = (float*)d_out;
    float* out_y    = out_xhat + (size_t)N_TRAIN * OUTD;

    float *p_dst, *p_agg, *p_deg, *p_h1, *p_qkv, *p_S, *p_av, *p_h2, *p_h3, *p_t, *p_bias;
    __nv_bfloat16 *A0, *A1, *B0;
    cudaGetSymbolAddress((void**)&p_dst, g_dst);
    cudaGetSymbolAddress((void**)&p_agg, g_agg);
    cudaGetSymbolAddress((void**)&p_deg, g_deg);
    cudaGetSymbolAddress((void**)&p_h1,  g_h1);
    cudaGetSymbolAddress((void**)&p_qkv, g_qkv);
    cudaGetSymbolAddress((void**)&p_S,   g_S);
    cudaGetSymbolAddress((void**)&p_av,  g_av);
    cudaGetSymbolAddress((void**)&p_h2,  g_h2);
    cudaGetSymbolAddress((void**)&p_h3,  g_h3);
    cudaGetSymbolAddress((void**)&p_t,   g_t);
    cudaGetSymbolAddress((void**)&p_bias,g_bias);
    cudaGetSymbolAddress((void**)&A0,    g_A0);
    cudaGetSymbolAddress((void**)&A1,    g_A1);
    cudaGetSymbolAddress((void**)&B0,    g_B0);

    cudaFuncSetAttribute(k_mma_gemm, cudaFuncAttributeMaxDynamicSharedMemorySize, GEMM_SMEM);

    const long n_dst = (long)N_TRAIN * DSTD;
    const long n_hd  = (long)N_TRAIN * HD;

    dim3 gHD (NP_HD  / 128, 16);    // 20 x 16 (M tile = 256)
    dim3 gQKV(NP_QKV / 128, 16);    // 60 x 16
    dim3 gS  (NP_S   / 128, 16);    // 32 x 16
    dim3 tb(32, 8);

    const long spDST = (long)4096 * (KP_DST / 2);
    const long spHD  = (long)4096 * (KP_HD  / 2);
    const long spS   = (long)4096 * (KP_S   / 2);

    // 1) concat dst features; bias concat for fused QKV
    k_concat<<<cdiv(n_dst, 256), 256>>>(trainf, yhat, p_dst);
    k_cat_bias<<<cdiv(NP_QKV, 256), 256>>>(bq, bk, bv, p_bias);

    // 2) neighbor mean (shared by conv3 & conv4)
    k_zero<<<cdiv(n_hd, 256), 256>>>(p_agg, n_hd);
    k_zero<<<cdiv(N_TRAIN, 256), 256>>>(p_deg, N_TRAIN);
    k_deg<<<cdiv(N_EDGES, 256), 256>>>(edst, p_deg);
    k_scatter<<<N_EDGES, 256>>>(gene, esrc, edst, p_agg);
    k_mean<<<cdiv(n_hd, 256), 256>>>(p_agg, p_deg);

    // 3) conv3 self: h1 = dst @ Wself3 + b3
    k_split_a3<<<cdiv(spDST, 256), 256>>>(p_dst, A0, 4096, DSTD, KP_DST, DSTD);
    k_split_bt3<<<dim3(KP_DST / 32, NP_HD / 32), tb>>>(Wself3, B0, DSTD, HD, KP_DST, NP_HD, HD);
    k_mma_gemm<<<gHD, 256, GEMM_SMEM>>>(A0, B0, p_h1, HD, 3L * KP_DST, b3, 1.0f, 0, 0);

    // conv3 neigh: h1 += agg @ Wneigh3  (A1 kept for conv4)
    k_split_a3<<<cdiv(spHD, 256), 256>>>(p_agg, A1, 4096, SRC, KP_HD, SRC);
    k_split_bt3<<<dim3(KP_HD / 32, NP_HD / 32), tb>>>(Wneigh3, B0, SRC, HD, KP_HD, NP_HD, HD);
    k_mma_gemm<<<gHD, 256, GEMM_SMEM>>>(A1, B0, p_h1, HD, 3L * KP_HD, nullptr, 1.0f, 1, 0);

    // 4) BN3 + leaky
    k_bn_partial<<<dim3(cdiv(HD, 256), 32), 256>>>(p_h1, HD);
    k_bn_final<<<cdiv(HD, 256), 256>>>(bn3g, bn3b, HD);
    k_bn_apply<<<cdiv(n_hd, 256), 256>>>(p_h1, p_h1, HD);

    // 5) fused QKV: qkv = h1 @ [Wq|Wk|Wv] + [bq|bk|bv]   (N = 7680)
    k_split_a3<<<cdiv(spHD, 256), 256>>>(p_h1, A0, 4096, HD, KP_HD, HD);
    k_split_bt3<<<dim3(KP_HD / 32, NP_HD / 32), tb>>>(Wq, B0, HD, HD, KP_HD, NP_HD, HD);
    k_split_bt3<<<dim3(KP_HD / 32, NP_HD / 32), tb>>>(Wk, B0 + (size_t)2560 * 3 * KP_HD, HD, HD, KP_HD, NP_HD, HD);
    k_split_bt3<<<dim3(KP_HD / 32, NP_HD / 32), tb>>>(Wv, B0 + (size_t)5120 * 3 * KP_HD, HD, HD, KP_HD, NP_HD, HD);
    k_mma_gemm<<<gQKV, 256, GEMM_SMEM>>>(A0, B0, p_qkv, NP_QKV, 3L * KP_HD, p_bias, 1.0f, 0, 0);

    // 6) S = softmax(q @ k^T * 0.02)
    //    q slice (pads are exact zeros): A-pattern, K=2560, ld=7680
    //    k slice: row-wise B-pattern
    k_split_a3<<<cdiv(spHD, 256), 256>>>(p_qkv, A0, 4096, KP_HD, KP_HD, NP_QKV);
    k_split_b3_rows<<<cdiv(spHD, 256), 256>>>(p_qkv + 2560, B0, 4096, KP_HD, KP_HD, NP_QKV);
    k_mma_gemm<<<gS, 256, GEMM_SMEM>>>(A0, B0, p_S, N_TRAIN, 3L * KP_HD, nullptr, 0.02f, 0, 0);
    k_softmax<<<N_TRAIN, 256>>>(p_S, N_TRAIN);

    // 7) AV = S @ V ; h2 = AV @ Wo + bo
    k_split_a3<<<cdiv(spS, 256), 256>>>(p_S, A0, 4096, N_TRAIN, KP_S, N_TRAIN);
    k_split_bt3<<<dim3(KP_S / 32, NP_HD / 32), tb>>>(p_qkv + 5120, B0, N_TRAIN, HD, KP_S, NP_HD, NP_QKV);
    k_mma_gemm<<<gHD, 256, GEMM_SMEM>>>(A0, B0, p_av, HD, 3L * KP_S, nullptr, 1.0f, 0, 0);

    k_split_a3<<<cdiv(spHD, 256), 256>>>(p_av, A0, 4096, HD, KP_HD, HD);
    k_split_bt3<<<dim3(KP_HD / 32, NP_HD / 32), tb>>>(Wo, B0, HD, HD, KP_HD, NP_HD, HD);
    k_mma_gemm<<<gHD, 256, GEMM_SMEM>>>(A0, B0, p_h2, HD, 3L * KP_HD, bo, 1.0f, 0, 0);

    // 8) LN + leaky
    k_ln_leaky<<<N_TRAIN, 256>>>(p_h2, ln2g, ln2b, HD);

    // 9) conv4: h3 = h2 @ Wself4 + b4 + agg @ Wneigh4
    k_split_a3<<<cdiv(spHD, 256), 256>>>(p_h2, A0, 4096, HD, KP_HD, HD);
    k_split_bt3<<<dim3(KP_HD / 32, NP_HD / 32), tb>>>(Wself4, B0, HD, OUTD, KP_HD, NP_HD, OUTD);
    k_mma_gemm<<<gHD, 256, GEMM_SMEM>>>(A0, B0, p_h3, OUTD, 3L * KP_HD, b4, 1.0f, 0, 0);
    k_split_bt3<<<dim3(KP_HD / 32, NP_HD / 32), tb>>>(Wneigh4, B0, SRC, OUTD, KP_HD, NP_HD, OUTD);
    k_mma_gemm<<<gHD, 256, GEMM_SMEM>>>(A1, B0, p_h3, OUTD, 3L * KP_HD, nullptr, 1.0f, 1, 0);

    // 10) BN4 + leaky -> x_hat
    k_bn_partial<<<dim3(cdiv(OUTD, 256), 32), 256>>>(p_h3, OUTD);
    k_bn_final<<<cdiv(OUTD, 256), 256>>>(bn4g, bn4b, OUTD);
    k_bn_apply<<<cdiv(n_hd, 256), 256>>>(p_h3, out_xhat, OUTD);

    // 11) head: t = relu(x_hat @ Wlin2 + blin2) ; y = t @ Wce + bce
    k_split_a3<<<cdiv(spHD, 256), 256>>>(out_xhat, A0, 4096, OUTD, KP_HD, OUTD);
    k_split_bt3<<<dim3(KP_HD / 32, NP_HD / 32), tb>>>(Wlin2, B0, OUTD, OUTD, KP_HD, NP_HD, OUTD);
    k_mma_gemm<<<gHD, 256, GEMM_SMEM>>>(A0, B0, p_t, OUTD, 3L * KP_HD, blin2, 1.0f, 0, 1);
    k_out_gemm<<<N_TRAIN, 256>>>(p_t, Wce, bce, out_y);
}

// round 14
// speedup vs baseline: 1.2309x; 1.2309x over previous
#include <cuda_runtime.h>
#include <cuda_bf16.h>
#include <math.h>
#include <stdint.h>

#define N_GENE  20000
#define N_TRAIN 4096
#define N_EDGES 131072
#define SRC     2500
#define DSTD    2675
#define HD      2500
#define OUTD    2500
#define NC      16
#define TRAINF  (DSTD - NC)   // 2659
#define EPS_F   1e-5f
#define SLOPE_F 0.01f

// padded K dims (multiple of 32 BEFORE the 3-slot interleave)
#define KP_DST  2688
#define KP_HD   2560
#define KP_S    4096
#define NP_HD   2560   // 20 col tiles
#define NP_QKV  7680   // 60 col tiles
#define NP_S    4096   // 32 col tiles

// ---------------- fp32 scratch ----------------------------------------------
__device__ float g_dst [(size_t)N_TRAIN * DSTD];
__device__ float g_agg [(size_t)N_TRAIN * SRC];
__device__ float g_deg [N_TRAIN];
__device__ float g_h1  [(size_t)N_TRAIN * HD];
__device__ float g_qkv [(size_t)N_TRAIN * NP_QKV];   // [q | k | v] fused, 2560 cols each
__device__ float g_S   [(size_t)N_TRAIN * N_TRAIN];
__device__ float g_av  [(size_t)N_TRAIN * HD];
__device__ float g_h2  [(size_t)N_TRAIN * HD];
__device__ float g_h3  [(size_t)N_TRAIN * OUTD];
__device__ float g_t   [(size_t)N_TRAIN * OUTD];
__device__ float g_bias[NP_QKV];
__device__ float g_psum[32 * HD];
__device__ float g_psq [32 * HD];
__device__ float g_bna [HD];
__device__ float g_bnc [HD];

// ---------------- bf16 3-slot interleaved buffers ----------------------------
// A pattern per k: [ah, al, ah] ; B pattern per k: [bh, bh, bl]
// dot(A',B') = ah*bh + al*bh + ah*bl = (ah+al)(bh+bl) - al*bl  (residual ~2^-16)
__device__ __nv_bfloat16 g_A0[(size_t)4096 * 3 * 4096];
__device__ __nv_bfloat16 g_A1[(size_t)4096 * 3 * KP_HD];
__device__ __nv_bfloat16 g_B0[(size_t)NP_QKV * 3 * KP_HD];   // 118 MB (fused QKV worst case)

// =============================================================================
// PTX helpers (portable compute_80-level only — tcgen05 rejected by this
// harness's compute_103 ptxas target)
// =============================================================================
__device__ __forceinline__ uint32_t smem_to_u32(const void* p) {
    uint32_t a;
    asm("{ .reg .u64 t; cvta.to.shared.u64 t, %1; cvt.u32.u64 %0, t; }" : "=r"(a) : "l"(p));
    return a;
}
__device__ __forceinline__ void cp16(uint32_t s, const void* g) {
    asm volatile("cp.async.cg.shared.global [%0], [%1], 16;" :: "r"(s), "l"(g));
}
__device__ __forceinline__ void cp_commit() { asm volatile("cp.async.commit_group;" ::: "memory"); }
__device__ __forceinline__ void cp_wait2()  { asm volatile("cp.async.wait_group 2;" ::: "memory"); }

__device__ __forceinline__ void ldsm4(uint32_t* r, uint32_t addr) {
    asm volatile("ldmatrix.sync.aligned.m8n8.x4.shared.b16 {%0,%1,%2,%3}, [%4];"
                 : "=r"(r[0]), "=r"(r[1]), "=r"(r[2]), "=r"(r[3]) : "r"(addr));
}
__device__ __forceinline__ void mma_bf16(float* c, const uint32_t* a, uint32_t b0, uint32_t b1) {
    asm volatile(
        "mma.sync.aligned.m16n8k16.row.col.f32.bf16.bf16.f32 "
        "{%0,%1,%2,%3}, {%4,%5,%6,%7}, {%8,%9}, {%0,%1,%2,%3};\n"
        : "+f"(c[0]), "+f"(c[1]), "+f"(c[2]), "+f"(c[3])
        : "r"(a[0]), "r"(a[1]), "r"(a[2]), "r"(a[3]), "r"(b0), "r"(b1));
}
__device__ __forceinline__ uint32_t pack2(__nv_bfloat16 lo, __nv_bfloat16 hi) {
    uint16_t a = __bfloat16_as_ushort(lo), b = __bfloat16_as_ushort(hi);
    return (uint32_t)a | ((uint32_t)b << 16);
}

// =============================================================================
// small utility kernels
// =============================================================================
__global__ void k_zero(float* p, long n) {
    long i = (long)blockIdx.x * blockDim.x + threadIdx.x;
    if (i < n) p[i] = 0.0f;
}

__global__ void k_concat(const float* __restrict__ tf, const float* __restrict__ yh,
                         float* __restrict__ dst) {
    long i = (long)blockIdx.x * blockDim.x + threadIdx.x;
    long total = (long)N_TRAIN * DSTD;
    if (i >= total) return;
    int r = (int)(i / DSTD), c = (int)(i % DSTD);
    dst[i] = (c < TRAINF) ? tf[(long)r * TRAINF + c] : yh[(long)r * NC + (c - TRAINF)];
}

__global__ void k_cat_bias(const float* __restrict__ bq, const float* __restrict__ bk,
                           const float* __restrict__ bv, float* __restrict__ o) {
    int i = blockIdx.x * 256 + threadIdx.x;
    if (i >= NP_QKV) return;
    int seg = i / 2560, j = i % 2560;
    const float* b = (seg == 0) ? bq : (seg == 1 ? bk : bv);
    o[i] = (j < HD) ? b[j] : 0.0f;
}

__global__ void k_deg(const int* __restrict__ di, float* __restrict__ deg) {
    int e = blockIdx.x * blockDim.x + threadIdx.x;
    if (e < N_EDGES) atomicAdd(&deg[di[e]], 1.0f);
}

__global__ void k_scatter(const float* __restrict__ gene, const int* __restrict__ si,
                          const int* __restrict__ di, float* __restrict__ agg) {
    int e = blockIdx.x;
    int s = si[e], d = di[e];
    const float* g = gene + (long)s * SRC;
    float* a = agg + (long)d * SRC;
    for (int c = threadIdx.x; c < SRC; c += blockDim.x)
        atomicAdd(&a[c], g[c]);
}

__global__ void k_mean(float* __restrict__ agg, const float* __restrict__ deg) {
    long i = (long)blockIdx.x * blockDim.x + threadIdx.x;
    long total = (long)N_TRAIN * SRC;
    if (i >= total) return;
    int r = (int)(i / SRC);
    agg[i] *= 1.0f / fmaxf(deg[r], 1.0f);
}

// fp32 [M x K] (row stride ldin) -> bf16 [M x 3*Kp], per-k pattern [ah, al, ah]
__global__ void k_split_a3(const float* __restrict__ in, __nv_bfloat16* __restrict__ out,
                           int M, int K, int Kp, int ldin) {
    long i = (long)blockIdx.x * blockDim.x + threadIdx.x;
    long total = (long)M * (Kp >> 1);
    if (i >= total) return;
    int half = Kp >> 1;
    int r = (int)(i / half), p = (int)(i % half);
    int c0 = 2 * p;
    float v0 = (c0     < K) ? in[(long)r * ldin + c0]     : 0.0f;
    float v1 = (c0 + 1 < K) ? in[(long)r * ldin + c0 + 1] : 0.0f;
    __nv_bfloat16 h0 = __float2bfloat16(v0);
    __nv_bfloat16 l0 = __float2bfloat16(v0 - __bfloat162float(h0));
    __nv_bfloat16 h1 = __float2bfloat16(v1);
    __nv_bfloat16 l1 = __float2bfloat16(v1 - __bfloat162float(h1));
    uint32_t* o = (uint32_t*)(out + (long)r * 3 * Kp + 3 * c0);
    o[0] = pack2(h0, l0);
    o[1] = pack2(h0, h1);
    o[2] = pack2(l1, h1);
}

// fp32 [M x K] (row stride ldin) -> bf16 [M x 3*Kp], per-k pattern [bh, bh, bl]
__global__ void k_split_b3_rows(const float* __restrict__ in, __nv_bfloat16* __restrict__ out,
                                int M, int K, int Kp, int ldin) {
    long i = (long)blockIdx.x * blockDim.x + threadIdx.x;
    long total = (long)M * (Kp >> 1);
    if (i >= total) return;
    int half = Kp >> 1;
    int r = (int)(i / half), p = (int)(i % half);
    int c0 = 2 * p;
    float v0 = (c0     < K) ? in[(long)r * ldin + c0]     : 0.0f;
    float v1 = (c0 + 1 < K) ? in[(long)r * ldin + c0 + 1] : 0.0f;
    __nv_bfloat16 h0 = __float2bfloat16(v0);
    __nv_bfloat16 l0 = __float2bfloat16(v0 - __bfloat162float(h0));
    __nv_bfloat16 h1 = __float2bfloat16(v1);
    __nv_bfloat16 l1 = __float2bfloat16(v1 - __bfloat162float(h1));
    uint32_t* o = (uint32_t*)(out + (long)r * 3 * Kp + 3 * c0);
    o[0] = pack2(h0, h0);
    o[1] = pack2(l0, h1);
    o[2] = pack2(h1, l1);
}

// fp32 [K x N] (row stride ldin) -> transposed bf16 [Np x 3*Kp], pattern [bh, bh, bl]
__global__ void k_split_bt3(const float* __restrict__ in, __nv_bfloat16* __restrict__ out,
                            int K, int N, int Kp, int Np, int ldin) {
    __shared__ float t[32][33];
    int k0 = blockIdx.x * 32, n0 = blockIdx.y * 32;
    int x = threadIdx.x, y = threadIdx.y;   // 32 x 8
    for (int i = y; i < 32; i += 8) {
        int k = k0 + i, n = n0 + x;
        t[i][x] = (k < K && n < N) ? in[(long)k * ldin + n] : 0.0f;
    }
    __syncthreads();
    long K2 = 3L * Kp;
    for (int i = y; i < 32; i += 8) {
        int n = n0 + i, k = k0 + x;
        float v = t[x][i];
        __nv_bfloat16 h = __float2bfloat16(v);
        __nv_bfloat16 l = __float2bfloat16(v - __bfloat162float(h));
        __nv_bfloat16* o = out + (long)n * K2 + 3 * k;
        o[0] = h; o[1] = h; o[2] = l;
    }
}

// =============================================================================
// bf16 mma.sync GEMM: C[M x N] = act( alpha*(A@B^T) + bias + (acc?C:0) )
// CTA tile 128x128, BK=32, 4-stage cp.async, 8 warps (4m x 2n), warp 32x64
// smem row stride 80B; 80KB smem + <=128 regs  =>  2 CTAs/SM (the R7 win config)
// =============================================================================
#define STAGES 4
#define STAGE_BYTES 20480
#define GEMM_SMEM (STAGES * STAGE_BYTES)

__device__ __forceinline__ void g_load_stage(uint32_t sbase, int stage,
    const __nv_bfloat16* A, const __nv_bfloat16* B, int m0, int n0, long K2, int kb)
{
    uint32_t sA = sbase + stage * STAGE_BYTES;
    uint32_t sB = sA + 10240;
    int tid = threadIdx.x;
    #pragma unroll
    for (int i = 0; i < 2; i++) {
        int idx = tid + i * 256;
        int r = idx >> 2, c = idx & 3;
        long gofs = (long)r * K2 + (long)kb * 32 + c * 8;
        cp16(sA + r * 80 + c * 16, (const char*)(A + (long)m0 * K2) + gofs * 2);
        cp16(sB + r * 80 + c * 16, (const char*)(B + (long)n0 * K2) + gofs * 2);
    }
}

__global__ __launch_bounds__(256, 2)
void k_mma_gemm(const __nv_bfloat16* __restrict__ A, const __nv_bfloat16* __restrict__ B,
                float* __restrict__ C, int N, long K2,
                const float* __restrict__ bias, float alpha, int acc, int act) {
    extern __shared__ char smem[];
    uint32_t sbase = smem_to_u32(smem);
    int tid = threadIdx.x;
    int warp = tid >> 5, lane = tid & 31;
    int wm = warp & 3, wn = warp >> 2;
    int m0 = blockIdx.y * 128, n0 = blockIdx.x * 128;

    float accf[2][8][4];
    #pragma unroll
    for (int i = 0; i < 2; i++)
        #pragma unroll
        for (int j = 0; j < 8; j++)
            #pragma unroll
            for (int l = 0; l < 4; l++) accf[i][j][l] = 0.0f;

    const int nkb = (int)(K2 >> 5);

    #pragma unroll
    for (int s = 0; s < STAGES - 1; s++) {
        if (s < nkb) g_load_stage(sbase, s, A, B, m0, n0, K2, s);
        cp_commit();
    }

    int lrow = lane & 15;
    int lcol = (lane >> 4) * 16;

    for (int kb = 0; kb < nkb; kb++) {
        cp_wait2();
        __syncthreads();
        int stage = kb & (STAGES - 1);
        uint32_t sA = sbase + stage * STAGE_BYTES;
        uint32_t sB = sA + 10240;

        #pragma unroll
        for (int kk = 0; kk < 2; kk++) {
            uint32_t a[2][4], bq[4][4];
            #pragma unroll
            for (int mi = 0; mi < 2; mi++)
                ldsm4(a[mi], sA + (wm * 32 + mi * 16 + lrow) * 80 + kk * 32 + lcol);
            #pragma unroll
            for (int nb = 0; nb < 4; nb++)
                ldsm4(bq[nb], sB + (wn * 64 + nb * 16 + lrow) * 80 + kk * 32 + lcol);
            #pragma unroll
            for (int mi = 0; mi < 2; mi++)
                #pragma unroll
                for (int nb = 0; nb < 4; nb++) {
                    mma_bf16(accf[mi][2 * nb],     a[mi], bq[nb][0], bq[nb][2]);
                    mma_bf16(accf[mi][2 * nb + 1], a[mi], bq[nb][1], bq[nb][3]);
                }
        }

        int nk = kb + STAGES - 1;
        if (nk < nkb) g_load_stage(sbase, nk & (STAGES - 1), A, B, m0, n0, K2, nk);
        cp_commit();
    }

    #pragma unroll
    for (int mi = 0; mi < 2; mi++) {
        int row0 = m0 + wm * 32 + mi * 16 + (lane >> 2);
        #pragma unroll
        for (int ni = 0; ni < 8; ni++) {
            int col = n0 + wn * 64 + ni * 8 + (lane & 3) * 2;
            if (col >= N) continue;
            float b0 = 0.f, b1 = 0.f;
            if (bias) { b0 = bias[col]; b1 = bias[col + 1]; }
            #pragma unroll
            for (int h = 0; h < 2; h++) {
                int row = row0 + h * 8;
                float v0 = accf[mi][ni][2 * h]     * alpha + b0;
                float v1 = accf[mi][ni][2 * h + 1] * alpha + b1;
                float* cp = &C[(long)row * N + col];
                if (acc) { float2 p = *(float2*)cp; v0 += p.x; v1 += p.y; }
                if (act) { v0 = fmaxf(v0, 0.f); v1 = fmaxf(v1, 0.f); }
                float2 o; o.x = v0; o.y = v1;
                *(float2*)cp = o;
            }
        }
    }
}

// =============================================================================
// softmax fused with 3-slot A-pattern split: reads fp32 S (exp written back in
// pass 2), emits normalized probs directly as bf16 triples into A0.
// n == Kp == 4096 (no padding needed).
// =============================================================================
__global__ void k_softmax_split(float* __restrict__ S, __nv_bfloat16* __restrict__ out, int n) {
    int r = blockIdx.x;
    float* row = S + (long)r * n;
    __shared__ float red[256];
    int tid = threadIdx.x;
    float mx = -INFINITY;
    for (int i = tid; i < n; i += 256) mx = fmaxf(mx, row[i]);
    red[tid] = mx; __syncthreads();
    for (int s = 128; s > 0; s >>= 1) {
        if (tid < s) red[tid] = fmaxf(red[tid], red[tid + s]);
        __syncthreads();
    }
    mx = red[0]; __syncthreads();
    float sum = 0.0f;
    for (int i = tid; i < n; i += 256) {
        float e = __expf(row[i] - mx);
        row[i] = e; sum += e;
    }
    red[tid] = sum; __syncthreads();
    for (int s = 128; s > 0; s >>= 1) {
        if (tid < s) red[tid] += red[tid + s];
        __syncthreads();
    }
    float inv = 1.0f / red[0];
    // pass 3: normalized value -> [ah, al, ah] triples, two elements per step
    uint32_t* obase = (uint32_t*)(out + (long)r * 3 * n);
    int half = n >> 1;
    for (int p = tid; p < half; p += 256) {
        int c0 = 2 * p;
        float v0 = row[c0] * inv;
        float v1 = row[c0 + 1] * inv;
        __nv_bfloat16 h0 = __float2bfloat16(v0);
        __nv_bfloat16 l0 = __float2bfloat16(v0 - __bfloat162float(h0));
        __nv_bfloat16 h1 = __float2bfloat16(v1);
        __nv_bfloat16 l1 = __float2bfloat16(v1 - __bfloat162float(h1));
        uint32_t* o = obase + 3 * p;
        o[0] = pack2(h0, l0);
        o[1] = pack2(h0, h1);
        o[2] = pack2(l1, h1);
    }
}

// =============================================================================
// BN / LN / head
// =============================================================================
__global__ void k_bn_partial(const float* __restrict__ X, int N) {
    int col = blockIdx.x * 256 + threadIdx.x;
    int rt = blockIdx.y;
    if (col >= N) return;
    const int RPT = N_TRAIN / 32;
    float s = 0.0f, q = 0.0f;
    int r0 = rt * RPT;
    for (int r = r0; r < r0 + RPT; r++) {
        float v = X[(long)r * N + col];
        s += v; q += v * v;
    }
    g_psum[rt * N + col] = s;
    g_psq [rt * N + col] = q;
}

__global__ void k_bn_final(const float* __restrict__ g, const float* __restrict__ b, int N) {
    int col = blockIdx.x * 256 + threadIdx.x;
    if (col >= N) return;
    float s = 0.0f, q = 0.0f;
    for (int t = 0; t < 32; t++) { s += g_psum[t * N + col]; q += g_psq[t * N + col]; }
    float m = s / (float)N_TRAIN;
    float var = q / (float)N_TRAIN - m * m;
    float sc = g[col] * rsqrtf(var + EPS_F);
    g_bna[col] = sc;
    g_bnc[col] = b[col] - m * sc;
}

__global__ void k_bn_apply(const float* __restrict__ X, float* __restrict__ Y, int N) {
    long i = (long)blockIdx.x * blockDim.x + threadIdx.x;
    long total = (long)N_TRAIN * N;
    if (i >= total) return;
    int col = (int)(i % N);
    float v = X[i] * g_bna[col] + g_bnc[col];
    Y[i] = (v >= 0.0f) ? v : SLOPE_F * v;
}

__global__ void k_ln_leaky(float* __restrict__ X, const float* __restrict__ g,
                           const float* __restrict__ b, int N) {
    int r = blockIdx.x;
    float* row = X + (long)r * N;
    __shared__ float r1[256], r2[256];
    int tid = threadIdx.x;
    float s = 0.0f, q = 0.0f;
    for (int i = tid; i < N; i += 256) { float v = row[i]; s += v; q += v * v; }
    r1[tid] = s; r2[tid] = q; __syncthreads();
    for (int st = 128; st > 0; st >>= 1) {
        if (tid < st) { r1[tid] += r1[tid + st]; r2[tid] += r2[tid + st]; }
        __syncthreads();
    }
    float m = r1[0] / (float)N;
    float var = r2[0] / (float)N - m * m;
    float inv = rsqrtf(var + EPS_F);
    for (int i = tid; i < N; i += 256) {
        float v = (row[i] - m) * inv * g[i] + b[i];
        row[i] = (v >= 0.0f) ? v : SLOPE_F * v;
    }
}

__global__ void k_out_gemm(const float* __restrict__ T, const float* __restrict__ W,
                           const float* __restrict__ bias, float* __restrict__ Y) {
    int r = blockIdx.x;
    int tid = threadIdx.x;
    int col = tid & 15, kg = tid >> 4;
    float acc = 0.0f;
    for (int k = kg; k < OUTD; k += 16)
        acc += T[(long)r * OUTD + k] * W[k * NC + col];
    __shared__ float red[256];
    red[tid] = acc; __syncthreads();
    if (kg == 0) {
        float s = 0.0f;
        for (int t = 0; t < 16; t++) s += red[col + 16 * t];
        Y[(long)r * NC + col] = s + bias[col];
    }
}

// =============================================================================
// launch
// =============================================================================
static inline int cdiv(long a, long b) { return (int)((a + b - 1) / b); }

extern "C" void kernel_launch(void* const* d_in, const int* in_sizes, int n_in,
                              void* d_out, int out_size) {
    const float* gene   = (const float*)d_in[0];
    const float* trainf = (const float*)d_in[1];
    const float* yhat   = (const float*)d_in[2];
    const int*   esrc   = (const int*)  d_in[3];
    const int*   edst   = (const int*)  d_in[4];
    const float* Wself3 = (const float*)d_in[5];
    const float* Wneigh3= (const float*)d_in[6];
    const float* b3     = (const float*)d_in[7];
    const float* bn3g   = (const float*)d_in[8];
    const float* bn3b   = (const float*)d_in[9];
    const float* Wq     = (const float*)d_in[10];
    const float* Wk     = (const float*)d_in[11];
    const float* Wv     = (const float*)d_in[12];
    const float* bq     = (const float*)d_in[13];
    const float* bk     = (const float*)d_in[14];
    const float* bv     = (const float*)d_in[15];
    const float* Wo     = (const float*)d_in[16];
    const float* bo     = (const float*)d_in[17];
    const float* ln2g   = (const float*)d_in[18];
    const float* ln2b   = (const float*)d_in[19];
    const float* Wself4 = (const float*)d_in[20];
    const float* Wneigh4= (const float*)d_in[21];
    const float* b4     = (const float*)d_in[22];
    const float* bn4g   = (const float*)d_in[23];
    const float* bn4b   = (const float*)d_in[24];
    const float* Wlin2  = (const float*)d_in[25];
    const float* blin2  = (const float*)d_in[26];
    const float* Wce    = (const float*)d_in[27];
    const float* bce    = (const float*)d_in[28];

    float* out_xhat = (float*)d_out;
    float* out_y    = out_xhat + (size_t)N_TRAIN * OUTD;

    float *p_dst, *p_agg, *p_deg, *p_h1, *p_qkv, *p_S, *p_av, *p_h2, *p_h3, *p_t, *p_bias;
    __nv_bfloat16 *A0, *A1, *B0;
    cudaGetSymbolAddress((void**)&p_dst, g_dst);
    cudaGetSymbolAddress((void**)&p_agg, g_agg);
    cudaGetSymbolAddress((void**)&p_deg, g_deg);
    cudaGetSymbolAddress((void**)&p_h1,  g_h1);
    cudaGetSymbolAddress((void**)&p_qkv, g_qkv);
    cudaGetSymbolAddress((void**)&p_S,   g_S);
    cudaGetSymbolAddress((void**)&p_av,  g_av);
    cudaGetSymbolAddress((void**)&p_h2,  g_h2);
    cudaGetSymbolAddress((void**)&p_h3,  g_h3);
    cudaGetSymbolAddress((void**)&p_t,   g_t);
    cudaGetSymbolAddress((void**)&p_bias,g_bias);
    cudaGetSymbolAddress((void**)&A0,    g_A0);
    cudaGetSymbolAddress((void**)&A1,    g_A1);
    cudaGetSymbolAddress((void**)&B0,    g_B0);

    cudaFuncSetAttribute(k_mma_gemm, cudaFuncAttributeMaxDynamicSharedMemorySize, GEMM_SMEM);

    const long n_dst = (long)N_TRAIN * DSTD;
    const long n_hd  = (long)N_TRAIN * HD;

    dim3 gHD (NP_HD  / 128, 32);    // 20 x 32  (128-row M tiles)
    dim3 gQKV(NP_QKV / 128, 32);    // 60 x 32
    dim3 gS  (NP_S   / 128, 32);    // 32 x 32
    dim3 tb(32, 8);

    const long spDST = (long)4096 * (KP_DST / 2);
    const long spHD  = (long)4096 * (KP_HD  / 2);

    // 1) concat dst features; bias concat for fused QKV
    k_concat<<<cdiv(n_dst, 256), 256>>>(trainf, yhat, p_dst);
    k_cat_bias<<<cdiv(NP_QKV, 256), 256>>>(bq, bk, bv, p_bias);

    // 2) neighbor mean (shared by conv3 & conv4)
    k_zero<<<cdiv(n_hd, 256), 256>>>(p_agg, n_hd);
    k_zero<<<cdiv(N_TRAIN, 256), 256>>>(p_deg, N_TRAIN);
    k_deg<<<cdiv(N_EDGES, 256), 256>>>(edst, p_deg);
    k_scatter<<<N_EDGES, 256>>>(gene, esrc, edst, p_agg);
    k_mean<<<cdiv(n_hd, 256), 256>>>(p_agg, p_deg);

    // 3) conv3 self: h1 = dst @ Wself3 + b3
    k_split_a3<<<cdiv(spDST, 256), 256>>>(p_dst, A0, 4096, DSTD, KP_DST, DSTD);
    k_split_bt3<<<dim3(KP_DST / 32, NP_HD / 32), tb>>>(Wself3, B0, DSTD, HD, KP_DST, NP_HD, HD);
    k_mma_gemm<<<gHD, 256, GEMM_SMEM>>>(A0, B0, p_h1, HD, 3L * KP_DST, b3, 1.0f, 0, 0);

    // conv3 neigh: h1 += agg @ Wneigh3  (A1 kept for conv4)
    k_split_a3<<<cdiv(spHD, 256), 256>>>(p_agg, A1, 4096, SRC, KP_HD, SRC);
    k_split_bt3<<<dim3(KP_HD / 32, NP_HD / 32), tb>>>(Wneigh3, B0, SRC, HD, KP_HD, NP_HD, HD);
    k_mma_gemm<<<gHD, 256, GEMM_SMEM>>>(A1, B0, p_h1, HD, 3L * KP_HD, nullptr, 1.0f, 1, 0);

    // 4) BN3 + leaky
    k_bn_partial<<<dim3(cdiv(HD, 256), 32), 256>>>(p_h1, HD);
    k_bn_final<<<cdiv(HD, 256), 256>>>(bn3g, bn3b, HD);
    k_bn_apply<<<cdiv(n_hd, 256), 256>>>(p_h1, p_h1, HD);

    // 5) fused QKV: qkv = h1 @ [Wq|Wk|Wv] + [bq|bk|bv]   (N = 7680)
    k_split_a3<<<cdiv(spHD, 256), 256>>>(p_h1, A0, 4096, HD, KP_HD, HD);
    k_split_bt3<<<dim3(KP_HD / 32, NP_HD / 32), tb>>>(Wq, B0, HD, HD, KP_HD, NP_HD, HD);
    k_split_bt3<<<dim3(KP_HD / 32, NP_HD / 32), tb>>>(Wk, B0 + (size_t)2560 * 3 * KP_HD, HD, HD, KP_HD, NP_HD, HD);
    k_split_bt3<<<dim3(KP_HD / 32, NP_HD / 32), tb>>>(Wv, B0 + (size_t)5120 * 3 * KP_HD, HD, HD, KP_HD, NP_HD, HD);
    k_mma_gemm<<<gQKV, 256, GEMM_SMEM>>>(A0, B0, p_qkv, NP_QKV, 3L * KP_HD, p_bias, 1.0f, 0, 0);

    // 6) S = softmax(q @ k^T * 0.02); softmax emits 3-slot split of S into A0
    k_split_a3<<<cdiv(spHD, 256), 256>>>(p_qkv, A0, 4096, KP_HD, KP_HD, NP_QKV);
    k_split_b3_rows<<<cdiv(spHD, 256), 256>>>(p_qkv + 2560, B0, 4096, KP_HD, KP_HD, NP_QKV);
    k_mma_gemm<<<gS, 256, GEMM_SMEM>>>(A0, B0, p_S, N_TRAIN, 3L * KP_HD, nullptr, 0.02f, 0, 0);
    k_softmax_split<<<N_TRAIN, 256>>>(p_S, A0, N_TRAIN);

    // 7) AV = S @ V ; h2 = AV @ Wo + bo
    k_split_bt3<<<dim3(KP_S / 32, NP_HD / 32), tb>>>(p_qkv + 5120, B0, N_TRAIN, HD, KP_S, NP_HD, NP_QKV);
    k_mma_gemm<<<gHD, 256, GEMM_SMEM>>>(A0, B0, p_av, HD, 3L * KP_S, nullptr, 1.0f, 0, 0);

    k_split_a3<<<cdiv(spHD, 256), 256>>>(p_av, A0, 4096, HD, KP_HD, HD);
    k_split_bt3<<<dim3(KP_HD / 32, NP_HD / 32), tb>>>(Wo, B0, HD, HD, KP_HD, NP_HD, HD);
    k_mma_gemm<<<gHD, 256, GEMM_SMEM>>>(A0, B0, p_h2, HD, 3L * KP_HD, bo, 1.0f, 0, 0);

    // 8) LN + leaky
    k_ln_leaky<<<N_TRAIN, 256>>>(p_h2, ln2g, ln2b, HD);

    // 9) conv4: h3 = h2 @ Wself4 + b4 + agg @ Wneigh4
    k_split_a3<<<cdiv(spHD, 256), 256>>>(p_h2, A0, 4096, HD, KP_HD, HD);
    k_split_bt3<<<dim3(KP_HD / 32, NP_HD / 32), tb>>>(Wself4, B0, HD, OUTD, KP_HD, NP_HD, OUTD);
    k_mma_gemm<<<gHD, 256, GEMM_SMEM>>>(A0, B0, p_h3, OUTD, 3L * KP_HD, b4, 1.0f, 0, 0);
    k_split_bt3<<<dim3(KP_HD / 32, NP_HD / 32), tb>>>(Wneigh4, B0, SRC, OUTD, KP_HD, NP_HD, OUTD);
    k_mma_gemm<<<gHD, 256, GEMM_SMEM>>>(A1, B0, p_h3, OUTD, 3L * KP_HD, nullptr, 1.0f, 1, 0);

    // 10) BN4 + leaky -> x_hat
    k_bn_partial<<<dim3(cdiv(OUTD, 256), 32), 256>>>(p_h3, OUTD);
    k_bn_final<<<cdiv(OUTD, 256), 256>>>(bn4g, bn4b, OUTD);
    k_bn_apply<<<cdiv(n_hd, 256), 256>>>(p_h3, out_xhat, OUTD);

    // 11) head: t = relu(x_hat @ Wlin2 + blin2) ; y = t @ Wce + bce
    k_split_a3<<<cdiv(spHD, 256), 256>>>(out_xhat, A0, 4096, OUTD, KP_HD, OUTD);
    k_split_bt3<<<dim3(KP_HD / 32, NP_HD / 32), tb>>>(Wlin2, B0, OUTD, OUTD, KP_HD, NP_HD, OUTD);
    k_mma_gemm<<<gHD, 256, GEMM_SMEM>>>(A0, B0, p_t, OUTD, 3L * KP_HD, blin2, 1.0f, 0, 1);
    k_out_gemm<<<N_TRAIN, 256>>>(p_t, Wce, bce, out_y);
}

// round 16
// speedup vs baseline: 1.2817x; 1.0413x over previous
#include <cuda_runtime.h>
#include <cuda_bf16.h>
#include <math.h>
#include <stdint.h>

#define N_GENE  20000
#define N_TRAIN 4096
#define N_EDGES 131072
#define SRC     2500
#define DSTD    2675
#define HD      2500
#define OUTD    2500
#define NC      16
#define TRAINF  (DSTD - NC)   // 2659
#define EPS_F   1e-5f
#define SLOPE_F 0.01f

// padded K dims (multiple of 32 BEFORE the 3-slot interleave)
#define KP_DST  2688
#define KP_HD   2560
#define KP_S    4096
#define NP_HD   2560        // 20 col tiles
#define NP_QKV  7680        // 60 col tiles
#define NP_S    4096        // 32 col tiles

// concat K' widths (in interleaved elems)
#define K2_C3   (3 * (KP_DST + KP_HD))   // 15744 (conv3: [dst|agg])
#define K2_C4   (3 * (KP_HD + KP_HD))    // 15360 (conv4: [h2|agg])
#define K2_HD   (3 * KP_HD)              // 7680
#define K2_S    (3 * KP_S)               // 12288

// ---------------- fp32 scratch ----------------------------------------------
__device__ float g_dst [(size_t)N_TRAIN * DSTD];
__device__ float g_agg [(size_t)N_TRAIN * SRC];
__device__ float g_qkv [(size_t)N_TRAIN * NP_QKV];   // [q | k | v], 2560 cols each
__device__ float g_S   [(size_t)N_TRAIN * N_TRAIN];
__device__ float g_av  [(size_t)N_TRAIN * HD];
__device__ float g_h2  [(size_t)N_TRAIN * HD];
__device__ float g_h3  [(size_t)N_TRAIN * OUTD];     // conv3/conv4 raw GEMM out
__device__ float g_t   [(size_t)N_TRAIN * OUTD];
__device__ float g_bias[NP_QKV];
__device__ float g_psum[32 * HD];
__device__ float g_psq [32 * HD];
__device__ float g_bna [HD];
__device__ float g_bnc [HD];

// edge bucketing
__device__ int g_cnt [N_TRAIN];
__device__ int g_off [N_TRAIN + 1];
__device__ int g_cur [N_TRAIN];
__device__ int g_ebuf[N_EDGES];       // src ids grouped by dst

// ---------------- bf16 3-slot interleaved buffers ----------------------------
// A per k: [ah, al, ah] ; B per k: [bh, bh, bl]
// dot = ah*bh + al*bh + ah*bl = (ah+al)(bh+bl) - al*bl  (residual ~2^-16)
__device__ __nv_bfloat16 g_A0[(size_t)N_TRAIN * K2_C3];     // 129 MB (max row 15744)
__device__ __nv_bfloat16 g_B0[(size_t)NP_QKV * K2_HD];      // 118 MB

// =============================================================================
// PTX helpers (portable compute_80-level only — tcgen05 rejected by this
// harness's compute_103 ptxas target)
// =============================================================================
__device__ __forceinline__ uint32_t smem_to_u32(const void* p) {
    uint32_t a;
    asm("{ .reg .u64 t; cvta.to.shared.u64 t, %1; cvt.u32.u64 %0, t; }" : "=r"(a) : "l"(p));
    return a;
}
__device__ __forceinline__ void cp16(uint32_t s, const void* g) {
    asm volatile("cp.async.cg.shared.global [%0], [%1], 16;" :: "r"(s), "l"(g));
}
__device__ __forceinline__ void cp_commit() { asm volatile("cp.async.commit_group;" ::: "memory"); }
__device__ __forceinline__ void cp_wait2()  { asm volatile("cp.async.wait_group 2;" ::: "memory"); }

__device__ __forceinline__ void ldsm4(uint32_t* r, uint32_t addr) {
    asm volatile("ldmatrix.sync.aligned.m8n8.x4.shared.b16 {%0,%1,%2,%3}, [%4];"
                 : "=r"(r[0]), "=r"(r[1]), "=r"(r[2]), "=r"(r[3]) : "r"(addr));
}
__device__ __forceinline__ void mma_bf16(float* c, const uint32_t* a, uint32_t b0, uint32_t b1) {
    asm volatile(
        "mma.sync.aligned.m16n8k16.row.col.f32.bf16.bf16.f32 "
        "{%0,%1,%2,%3}, {%4,%5,%6,%7}, {%8,%9}, {%0,%1,%2,%3};\n"
        : "+f"(c[0]), "+f"(c[1]), "+f"(c[2]), "+f"(c[3])
        : "r"(a[0]), "r"(a[1]), "r"(a[2]), "r"(a[3]), "r"(b0), "r"(b1));
}
__device__ __forceinline__ uint32_t pack2(__nv_bfloat16 lo, __nv_bfloat16 hi) {
    uint16_t a = __bfloat16_as_ushort(lo), b = __bfloat16_as_ushort(hi);
    return (uint32_t)a | ((uint32_t)b << 16);
}
__device__ __forceinline__ float leaky(float v) { return (v >= 0.0f) ? v : SLOPE_F * v; }

// emit one A-pattern pair triple: [h0,l0,h0,h1,l1,h1]
__device__ __forceinline__ void emit_a3(uint32_t* o, float v0, float v1) {
    __nv_bfloat16 h0 = __float2bfloat16(v0);
    __nv_bfloat16 l0 = __float2bfloat16(v0 - __bfloat162float(h0));
    __nv_bfloat16 h1 = __float2bfloat16(v1);
    __nv_bfloat16 l1 = __float2bfloat16(v1 - __bfloat162float(h1));
    o[0] = pack2(h0, l0);
    o[1] = pack2(h0, h1);
    o[2] = pack2(l1, h1);
}
// emit one B-pattern pair triple: [h0,h0,l0,h1,h1,l1]
__device__ __forceinline__ void emit_b3(uint32_t* o, float v0, float v1) {
    __nv_bfloat16 h0 = __float2bfloat16(v0);
    __nv_bfloat16 l0 = __float2bfloat16(v0 - __bfloat162float(h0));
    __nv_bfloat16 h1 = __float2bfloat16(v1);
    __nv_bfloat16 l1 = __float2bfloat16(v1 - __bfloat162float(h1));
    o[0] = pack2(h0, h0);
    o[1] = pack2(l0, h1);
    o[2] = pack2(h1, l1);
}

// =============================================================================
// small utility kernels
// =============================================================================
__global__ void k_zero_i(int* p, int n) {
    int i = blockIdx.x * blockDim.x + threadIdx.x;
    if (i < n) p[i] = 0;
}

__global__ void k_concat(const float* __restrict__ tf, const float* __restrict__ yh,
                         float* __restrict__ dst) {
    long i = (long)blockIdx.x * blockDim.x + threadIdx.x;
    long total = (long)N_TRAIN * DSTD;
    if (i >= total) return;
    int r = (int)(i / DSTD), c = (int)(i % DSTD);
    dst[i] = (c < TRAINF) ? tf[(long)r * TRAINF + c] : yh[(long)r * NC + (c - TRAINF)];
}

__global__ void k_cat_bias(const float* __restrict__ bq, const float* __restrict__ bk,
                           const float* __restrict__ bv, float* __restrict__ o) {
    int i = blockIdx.x * 256 + threadIdx.x;
    if (i >= NP_QKV) return;
    int seg = i / 2560, j = i % 2560;
    const float* b = (seg == 0) ? bq : (seg == 1 ? bk : bv);
    o[i] = (j < HD) ? b[j] : 0.0f;
}

// ---- edge bucketing: count -> scan -> fill -> gather ----
__global__ void k_count(const int* __restrict__ di, int* __restrict__ cnt) {
    int e = blockIdx.x * blockDim.x + threadIdx.x;
    if (e < N_EDGES) atomicAdd(&cnt[di[e]], 1);
}

__global__ void k_scan() {    // one block, 1024 threads, 4 elems each
    __shared__ int part[1024];
    int t = threadIdx.x;
    int base = t * 4;
    int v[4], s = 0;
    #pragma unroll
    for (int i = 0; i < 4; i++) { v[i] = s; s += g_cnt[base + i]; }
    part[t] = s;
    __syncthreads();
    for (int d = 1; d < 1024; d <<= 1) {
        int x = 0;
        if (t >= d) x = part[t - d];
        __syncthreads();
        if (t >= d) part[t] += x;
        __syncthreads();
    }
    int pre = (t > 0) ? part[t - 1] : 0;
    #pragma unroll
    for (int i = 0; i < 4; i++) {
        g_off[base + i] = pre + v[i];
        g_cur[base + i] = pre + v[i];
    }
    if (t == 1023) g_off[4096] = part[1023];
}

__global__ void k_fill(const int* __restrict__ si, const int* __restrict__ di) {
    int e = blockIdx.x * blockDim.x + threadIdx.x;
    if (e >= N_EDGES) return;
    int d = di[e];
    int p = atomicAdd(&g_cur[d], 1);
    g_ebuf[p] = si[e];
}

// block per dst row: sum grouped src rows in registers, write mean once
__global__ void k_gather(const float* __restrict__ gene, float* __restrict__ agg) {
    int d = blockIdx.x;
    int beg = g_off[d], end = g_off[d + 1];
    int cnt = end - beg;
    int tid = threadIdx.x;
    float acc[10];
    #pragma unroll
    for (int u = 0; u < 10; u++) acc[u] = 0.0f;
    for (int e = beg; e < end; e++) {
        const float* gr = gene + (long)g_ebuf[e] * SRC;
        #pragma unroll
        for (int u = 0; u < 10; u++) {
            int c = tid + u * 256;
            if (c < SRC) acc[u] += gr[c];
        }
    }
    float inv = 1.0f / fmaxf((float)cnt, 1.0f);
    float* ar = agg + (long)d * SRC;
    #pragma unroll
    for (int u = 0; u < 10; u++) {
        int c = tid + u * 256;
        if (c < SRC) ar[c] = acc[u] * inv;
    }
}

// =============================================================================
// split kernels (all take output row stride K2row + element offset out_off)
// =============================================================================
// fp32 [M x K] (row stride ldin) -> A-pattern triples
__global__ void k_split_a3(const float* __restrict__ in, __nv_bfloat16* __restrict__ out,
                           int M, int K, int Kp, int ldin, long K2row, long out_off) {
    long i = (long)blockIdx.x * blockDim.x + threadIdx.x;
    long total = (long)M * (Kp >> 1);
    if (i >= total) return;
    int half = Kp >> 1;
    int r = (int)(i / half), p = (int)(i % half);
    int c0 = 2 * p;
    float v0 = (c0     < K) ? in[(long)r * ldin + c0]     : 0.0f;
    float v1 = (c0 + 1 < K) ? in[(long)r * ldin + c0 + 1] : 0.0f;
    emit_a3((uint32_t*)(out + (long)r * K2row + out_off + 3 * c0), v0, v1);
}

// fp32 [M x K] (row stride ldin) -> B-pattern triples (operand already B^T rows)
__global__ void k_split_b3_rows(const float* __restrict__ in, __nv_bfloat16* __restrict__ out,
                                int M, int K, int Kp, int ldin, long K2row, long out_off) {
    long i = (long)blockIdx.x * blockDim.x + threadIdx.x;
    long total = (long)M * (Kp >> 1);
    if (i >= total) return;
    int half = Kp >> 1;
    int r = (int)(i / half), p = (int)(i % half);
    int c0 = 2 * p;
    float v0 = (c0     < K) ? in[(long)r * ldin + c0]     : 0.0f;
    float v1 = (c0 + 1 < K) ? in[(long)r * ldin + c0 + 1] : 0.0f;
    emit_b3((uint32_t*)(out + (long)r * K2row + out_off + 3 * c0), v0, v1);
}

// fp32 [K x N] (row stride ldin) -> transposed B-pattern triples [Np rows]
__global__ void k_split_bt3(const float* __restrict__ in, __nv_bfloat16* __restrict__ out,
                            int K, int N, int Kp, int Np, int ldin, long K2row, long out_off) {
    __shared__ float t[32][33];
    int k0 = blockIdx.x * 32, n0 = blockIdx.y * 32;
    int x = threadIdx.x, y = threadIdx.y;   // 32 x 8
    for (int i = y; i < 32; i += 8) {
        int k = k0 + i, n = n0 + x;
        t[i][x] = (k < K && n < N) ? in[(long)k * ldin + n] : 0.0f;
    }
    __syncthreads();
    for (int i = y; i < 32; i += 8) {
        int n = n0 + i, k = k0 + x;
        float v = t[x][i];
        __nv_bfloat16 h = __float2bfloat16(v);
        __nv_bfloat16 l = __float2bfloat16(v - __bfloat162float(h));
        __nv_bfloat16* o = out + (long)n * K2row + out_off + 3 * k;
        o[0] = h; o[1] = h; o[2] = l;
    }
}

// =============================================================================
// bf16 mma.sync GEMM: C[M x N] = act( alpha*(A@B^T) + bias + (acc?C:0) )
// CTA tile 128x128, BK=32, 4-stage cp.async, 8 warps (4m x 2n), warp 32x64
// smem row stride 80B; 80KB smem + <=128 regs  =>  2 CTAs/SM (proven config)
// =============================================================================
#define STAGES 4
#define STAGE_BYTES 20480
#define GEMM_SMEM (STAGES * STAGE_BYTES)

__device__ __forceinline__ void g_load_stage(uint32_t sbase, int stage,
    const __nv_bfloat16* A, const __nv_bfloat16* B, int m0, int n0, long K2, int kb)
{
    uint32_t sA = sbase + stage * STAGE_BYTES;
    uint32_t sB = sA + 10240;
    int tid = threadIdx.x;
    #pragma unroll
    for (int i = 0; i < 2; i++) {
        int idx = tid + i * 256;
        int r = idx >> 2, c = idx & 3;
        long gofs = (long)r * K2 + (long)kb * 32 + c * 8;
        cp16(sA + r * 80 + c * 16, (const char*)(A + (long)m0 * K2) + gofs * 2);
        cp16(sB + r * 80 + c * 16, (const char*)(B + (long)n0 * K2) + gofs * 2);
    }
}

__global__ __launch_bounds__(256, 2)
void k_mma_gemm(const __nv_bfloat16* __restrict__ A, const __nv_bfloat16* __restrict__ B,
                float* __restrict__ C, int N, long K2,
                const float* __restrict__ bias, float alpha, int acc, int act) {
    extern __shared__ char smem[];
    uint32_t sbase = smem_to_u32(smem);
    int tid = threadIdx.x;
    int warp = tid >> 5, lane = tid & 31;
    int wm = warp & 3, wn = warp >> 2;
    int m0 = blockIdx.y * 128, n0 = blockIdx.x * 128;

    float accf[2][8][4];
    #pragma unroll
    for (int i = 0; i < 2; i++)
        #pragma unroll
        for (int j = 0; j < 8; j++)
            #pragma unroll
            for (int l = 0; l < 4; l++) accf[i][j][l] = 0.0f;

    const int nkb = (int)(K2 >> 5);

    #pragma unroll
    for (int s = 0; s < STAGES - 1; s++) {
        if (s < nkb) g_load_stage(sbase, s, A, B, m0, n0, K2, s);
        cp_commit();
    }

    int lrow = lane & 15;
    int lcol = (lane >> 4) * 16;

    for (int kb = 0; kb < nkb; kb++) {
        cp_wait2();
        __syncthreads();
        int stage = kb & (STAGES - 1);
        uint32_t sA = sbase + stage * STAGE_BYTES;
        uint32_t sB = sA + 10240;

        #pragma unroll
        for (int kk = 0; kk < 2; kk++) {
            uint32_t a[2][4], bq[4][4];
            #pragma unroll
            for (int mi = 0; mi < 2; mi++)
                ldsm4(a[mi], sA + (wm * 32 + mi * 16 + lrow) * 80 + kk * 32 + lcol);
            #pragma unroll
            for (int nb = 0; nb < 4; nb++)
                ldsm4(bq[nb], sB + (wn * 64 + nb * 16 + lrow) * 80 + kk * 32 + lcol);
            #pragma unroll
            for (int mi = 0; mi < 2; mi++)
                #pragma unroll
                for (int nb = 0; nb < 4; nb++) {
                    mma_bf16(accf[mi][2 * nb],     a[mi], bq[nb][0], bq[nb][2]);
                    mma_bf16(accf[mi][2 * nb + 1], a[mi], bq[nb][1], bq[nb][3]);
                }
        }

        int nk = kb + STAGES - 1;
        if (nk < nkb) g_load_stage(sbase, nk & (STAGES - 1), A, B, m0, n0, K2, nk);
        cp_commit();
    }

    #pragma unroll
    for (int mi = 0; mi < 2; mi++) {
        int row0 = m0 + wm * 32 + mi * 16 + (lane >> 2);
        #pragma unroll
        for (int ni = 0; ni < 8; ni++) {
            int col = n0 + wn * 64 + ni * 8 + (lane & 3) * 2;
            if (col >= N) continue;
            float b0 = 0.f, b1 = 0.f;
            if (bias) { b0 = bias[col]; b1 = bias[col + 1]; }
            #pragma unroll
            for (int h = 0; h < 2; h++) {
                int row = row0 + h * 8;
                float v0 = accf[mi][ni][2 * h]     * alpha + b0;
                float v1 = accf[mi][ni][2 * h + 1] * alpha + b1;
                float* cp = &C[(long)row * N + col];
                if (acc) { float2 p = *(float2*)cp; v0 += p.x; v1 += p.y; }
                if (act) { v0 = fmaxf(v0, 0.f); v1 = fmaxf(v1, 0.f); }
                float2 o; o.x = v0; o.y = v1;
                *(float2*)cp = o;
            }
        }
    }
}

// =============================================================================
// softmax fused with A-pattern split (row stride 3n = K2_S)
// =============================================================================
__global__ void k_softmax_split(float* __restrict__ S, __nv_bfloat16* __restrict__ out, int n) {
    int r = blockIdx.x;
    float* row = S + (long)r * n;
    __shared__ float red[256];
    int tid = threadIdx.x;
    float mx = -INFINITY;
    for (int i = tid; i < n; i += 256) mx = fmaxf(mx, row[i]);
    red[tid] = mx; __syncthreads();
    for (int s = 128; s > 0; s >>= 1) {
        if (tid < s) red[tid] = fmaxf(red[tid], red[tid + s]);
        __syncthreads();
    }
    mx = red[0]; __syncthreads();
    float sum = 0.0f;
    for (int i = tid; i < n; i += 256) {
        float e = __expf(row[i] - mx);
        row[i] = e; sum += e;
    }
    red[tid] = sum; __syncthreads();
    for (int s = 128; s > 0; s >>= 1) {
        if (tid < s) red[tid] += red[tid + s];
        __syncthreads();
    }
    float inv = 1.0f / red[0];
    uint32_t* obase = (uint32_t*)(out + (long)r * 3 * n);
    int half = n >> 1;
    for (int p = tid; p < half; p += 256) {
        int c0 = 2 * p;
        emit_a3(obase + 3 * p, row[c0] * inv, row[c0 + 1] * inv);
    }
}

// =============================================================================
// BatchNorm: partial sums -> scale/shift -> fused apply+leaky+A-split
// =============================================================================
__global__ void k_bn_partial(const float* __restrict__ X, int N) {
    int col = blockIdx.x * 256 + threadIdx.x;
    int rt = blockIdx.y;
    if (col >= N) return;
    const int RPT = N_TRAIN / 32;
    float s = 0.0f, q = 0.0f;
    int r0 = rt * RPT;
    for (int r = r0; r < r0 + RPT; r++) {
        float v = X[(long)r * N + col];
        s += v; q += v * v;
    }
    g_psum[rt * N + col] = s;
    g_psq [rt * N + col] = q;
}

__global__ void k_bn_final(const float* __restrict__ g, const float* __restrict__ b, int N) {
    int col = blockIdx.x * 256 + threadIdx.x;
    if (col >= N) return;
    float s = 0.0f, q = 0.0f;
    for (int t = 0; t < 32; t++) { s += g_psum[t * N + col]; q += g_psq[t * N + col]; }
    float m = s / (float)N_TRAIN;
    float var = q / (float)N_TRAIN - m * m;
    float sc = g[col] * rsqrtf(var + EPS_F);
    g_bna[col] = sc;
    g_bnc[col] = b[col] - m * sc;
}

// BN apply + leaky -> A-pattern split only (h fp32 never materialized)
__global__ void k_bn_split(const float* __restrict__ X, __nv_bfloat16* __restrict__ out,
                           int N, int Kp, long K2row) {
    long i = (long)blockIdx.x * blockDim.x + threadIdx.x;
    long total = (long)N_TRAIN * (Kp >> 1);
    if (i >= total) return;
    int half = Kp >> 1;
    int r = (int)(i / half), p = (int)(i % half);
    int c0 = 2 * p;
    float v0 = (c0     < N) ? leaky(X[(long)r * N + c0]     * g_bna[c0]     + g_bnc[c0])     : 0.0f;
    float v1 = (c0 + 1 < N) ? leaky(X[(long)r * N + c0 + 1] * g_bna[c0 + 1] + g_bnc[c0 + 1]) : 0.0f;
    emit_a3((uint32_t*)(out + (long)r * K2row + 3 * c0), v0, v1);
}

// BN apply + leaky -> fp32 output AND A-pattern split (for x_hat)
__global__ void k_bn_split_out(const float* __restrict__ X, float* __restrict__ Y,
                               __nv_bfloat16* __restrict__ out, int N, int Kp, long K2row) {
    long i = (long)blockIdx.x * blockDim.x + threadIdx.x;
    long total = (long)N_TRAIN * (Kp >> 1);
    if (i >= total) return;
    int half = Kp >> 1;
    int r = (int)(i / half), p = (int)(i % half);
    int c0 = 2 * p;
    float v0 = 0.0f, v1 = 0.0f;
    if (c0 < N) {
        v0 = leaky(X[(long)r * N + c0] * g_bna[c0] + g_bnc[c0]);
        Y[(long)r * N + c0] = v0;
    }
    if (c0 + 1 < N) {
        v1 = leaky(X[(long)r * N + c0 + 1] * g_bna[c0 + 1] + g_bnc[c0 + 1]);
        Y[(long)r * N + c0 + 1] = v1;
    }
    emit_a3((uint32_t*)(out + (long)r * K2row + 3 * c0), v0, v1);
}

// LayerNorm + leaky -> A-pattern split (h2 fp32 read, split written)
__global__ void k_ln_split(const float* __restrict__ X, const float* __restrict__ g,
                           const float* __restrict__ b, __nv_bfloat16* __restrict__ out,
                           int N, int Kp, long K2row) {
    int r = blockIdx.x;
    const float* row = X + (long)r * N;
    __shared__ float r1[256], r2[256];
    int tid = threadIdx.x;
    float s = 0.0f, q = 0.0f;
    for (int i = tid; i < N; i += 256) { float v = row[i]; s += v; q += v * v; }
    r1[tid] = s; r2[tid] = q; __syncthreads();
    for (int st = 128; st > 0; st >>= 1) {
        if (tid < st) { r1[tid] += r1[tid + st]; r2[tid] += r2[tid + st]; }
        __syncthreads();
    }
    float m = r1[0] / (float)N;
    float var = r2[0] / (float)N - m * m;
    float inv = rsqrtf(var + EPS_F);
    uint32_t* obase = (uint32_t*)(out + (long)r * K2row);
    int half = Kp >> 1;
    for (int p = tid; p < half; p += 256) {
        int c0 = 2 * p;
        float v0 = (c0     < N) ? leaky((row[c0]     - m) * inv * g[c0]     + b[c0])     : 0.0f;
        float v1 = (c0 + 1 < N) ? leaky((row[c0 + 1] - m) * inv * g[c0 + 1] + b[c0 + 1]) : 0.0f;
        emit_a3(obase + 3 * p, v0, v1);
    }
}

__global__ void k_out_gemm(const float* __restrict__ T, const float* __restrict__ W,
                           const float* __restrict__ bias, float* __restrict__ Y) {
    int r = blockIdx.x;
    int tid = threadIdx.x;
    int col = tid & 15, kg = tid >> 4;
    float acc = 0.0f;
    for (int k = kg; k < OUTD; k += 16)
        acc += T[(long)r * OUTD + k] * W[k * NC + col];
    __shared__ float red[256];
    red[tid] = acc; __syncthreads();
    if (kg == 0) {
        float s = 0.0f;
        for (int t = 0; t < 16; t++) s += red[col + 16 * t];
        Y[(long)r * NC + col] = s + bias[col];
    }
}

// =============================================================================
// launch
// =============================================================================
static inline int cdiv(long a, long b) { return (int)((a + b - 1) / b); }

extern "C" void kernel_launch(void* const* d_in, const int* in_sizes, int n_in,
                              void* d_out, int out_size) {
    const float* gene   = (const float*)d_in[0];
    const float* trainf = (const float*)d_in[1];
    const float* yhat   = (const float*)d_in[2];
    const int*   esrc   = (const int*)  d_in[3];
    const int*   edst   = (const int*)  d_in[4];
    const float* Wself3 = (const float*)d_in[5];
    const float* Wneigh3= (const float*)d_in[6];
    const float* b3     = (const float*)d_in[7];
    const float* bn3g   = (const float*)d_in[8];
    const float* bn3b   = (const float*)d_in[9];
    const float* Wq     = (const float*)d_in[10];
    const float* Wk     = (const float*)d_in[11];
    const float* Wv     = (const float*)d_in[12];
    const float* bq     = (const float*)d_in[13];
    const float* bk     = (const float*)d_in[14];
    const float* bv     = (const float*)d_in[15];
    const float* Wo     = (const float*)d_in[16];
    const float* bo     = (const float*)d_in[17];
    const float* ln2g   = (const float*)d_in[18];
    const float* ln2b   = (const float*)d_in[19];
    const float* Wself4 = (const float*)d_in[20];
    const float* Wneigh4= (const float*)d_in[21];
    const float* b4     = (const float*)d_in[22];
    const float* bn4g   = (const float*)d_in[23];
    const float* bn4b   = (const float*)d_in[24];
    const float* Wlin2  = (const float*)d_in[25];
    const float* blin2  = (const float*)d_in[26];
    const float* Wce    = (const float*)d_in[27];
    const float* bce    = (const float*)d_in[28];

    float* out_xhat = (float*)d_out;
    float* out_y    = out_xhat + (size_t)N_TRAIN * OUTD;

    float *p_dst, *p_agg, *p_qkv, *p_S, *p_av, *p_h2, *p_h3, *p_t, *p_bias;
    int* p_cnt;
    __nv_bfloat16 *A0, *B0;
    cudaGetSymbolAddress((void**)&p_dst, g_dst);
    cudaGetSymbolAddress((void**)&p_agg, g_agg);
    cudaGetSymbolAddress((void**)&p_qkv, g_qkv);
    cudaGetSymbolAddress((void**)&p_S,   g_S);
    cudaGetSymbolAddress((void**)&p_av,  g_av);
    cudaGetSymbolAddress((void**)&p_h2,  g_h2);
    cudaGetSymbolAddress((void**)&p_h3,  g_h3);
    cudaGetSymbolAddress((void**)&p_t,   g_t);
    cudaGetSymbolAddress((void**)&p_bias,g_bias);
    cudaGetSymbolAddress((void**)&p_cnt, g_cnt);
    cudaGetSymbolAddress((void**)&A0,    g_A0);
    cudaGetSymbolAddress((void**)&B0,    g_B0);

    cudaFuncSetAttribute(k_mma_gemm, cudaFuncAttributeMaxDynamicSharedMemorySize, GEMM_SMEM);

    const long n_dst = (long)N_TRAIN * DSTD;

    dim3 gHD (NP_HD  / 128, 32);    // 20 x 32
    dim3 gQKV(NP_QKV / 128, 32);    // 60 x 32
    dim3 gS  (NP_S   / 128, 32);    // 32 x 32
    dim3 tb(32, 8);

    const long spDST = (long)N_TRAIN * (KP_DST / 2);
    const long spHD  = (long)N_TRAIN * (KP_HD  / 2);
    const long bnHD  = (long)N_TRAIN * (KP_HD  / 2);

    // 1) concat dst features; bias concat for fused QKV
    k_concat<<<cdiv(n_dst, 256), 256>>>(trainf, yhat, p_dst);
    k_cat_bias<<<cdiv(NP_QKV, 256), 256>>>(bq, bk, bv, p_bias);

    // 2) neighbor mean via bucketed gather (no giant atomic scatter)
    k_zero_i<<<16, 256>>>(p_cnt, N_TRAIN);
    k_count<<<cdiv(N_EDGES, 256), 256>>>(edst, p_cnt);
    k_scan<<<1, 1024>>>();
    k_fill<<<cdiv(N_EDGES, 256), 256>>>(esrc, edst);
    k_gather<<<N_TRAIN, 256>>>(gene, p_agg);

    // 3) conv3 (merged): h3 = [dst|agg] @ [Wself3;Wneigh3] + b3
    k_split_a3<<<cdiv(spDST, 256), 256>>>(p_dst, A0, N_TRAIN, DSTD, KP_DST, DSTD, K2_C3, 0);
    k_split_a3<<<cdiv(spHD, 256), 256>>>(p_agg, A0, N_TRAIN, SRC, KP_HD, SRC, K2_C3, 3 * KP_DST);
    k_split_bt3<<<dim3(KP_DST / 32, NP_HD / 32), tb>>>(Wself3, B0, DSTD, HD, KP_DST, NP_HD, HD, K2_C3, 0);
    k_split_bt3<<<dim3(KP_HD / 32, NP_HD / 32), tb>>>(Wneigh3, B0, SRC, HD, KP_HD, NP_HD, HD, K2_C3, 3 * KP_DST);
    k_mma_gemm<<<gHD, 256, GEMM_SMEM>>>(A0, B0, p_h3, HD, K2_C3, b3, 1.0f, 0, 0);

    // 4) BN3 + leaky fused into QKV A-split (h1 fp32 never written)
    k_bn_partial<<<dim3(cdiv(HD, 256), 32), 256>>>(p_h3, HD);
    k_bn_final<<<cdiv(HD, 256), 256>>>(bn3g, bn3b, HD);
    k_bn_split<<<cdiv(bnHD, 256), 256>>>(p_h3, A0, HD, KP_HD, K2_HD);

    // 5) fused QKV: qkv = h1 @ [Wq|Wk|Wv] + [bq|bk|bv]   (N = 7680)
    k_split_bt3<<<dim3(KP_HD / 32, NP_HD / 32), tb>>>(Wq, B0, HD, HD, KP_HD, NP_HD, HD, K2_HD, 0);
    k_split_bt3<<<dim3(KP_HD / 32, NP_HD / 32), tb>>>(Wk, B0 + (size_t)2560 * K2_HD, HD, HD, KP_HD, NP_HD, HD, K2_HD, 0);
    k_split_bt3<<<dim3(KP_HD / 32, NP_HD / 32), tb>>>(Wv, B0 + (size_t)5120 * K2_HD, HD, HD, KP_HD, NP_HD, HD, K2_HD, 0);
    k_mma_gemm<<<gQKV, 256, GEMM_SMEM>>>(A0, B0, p_qkv, NP_QKV, K2_HD, p_bias, 1.0f, 0, 0);

    // 6) S = softmax(q @ k^T * 0.02); softmax emits A-split of S into A0
    k_split_a3<<<cdiv(spHD, 256), 256>>>(p_qkv, A0, N_TRAIN, KP_HD, KP_HD, NP_QKV, K2_HD, 0);
    k_split_b3_rows<<<cdiv(spHD, 256), 256>>>(p_qkv + 2560, B0, N_TRAIN, KP_HD, KP_HD, NP_QKV, K2_HD, 0);
    k_mma_gemm<<<gS, 256, GEMM_SMEM>>>(A0, B0, p_S, N_TRAIN, K2_HD, nullptr, 0.02f, 0, 0);
    k_softmax_split<<<N_TRAIN, 256>>>(p_S, A0, N_TRAIN);

    // 7) AV = S @ V ; h2 = AV @ Wo + bo
    k_split_bt3<<<dim3(KP_S / 32, NP_HD / 32), tb>>>(p_qkv + 5120, B0, N_TRAIN, HD, KP_S, NP_HD, NP_QKV, K2_S, 0);
    k_mma_gemm<<<gHD, 256, GEMM_SMEM>>>(A0, B0, p_av, HD, K2_S, nullptr, 1.0f, 0, 0);

    k_split_a3<<<cdiv(spHD, 256), 256>>>(p_av, A0, N_TRAIN, HD, KP_HD, HD, K2_HD, 0);
    k_split_bt3<<<dim3(KP_HD / 32, NP_HD / 32), tb>>>(Wo, B0, HD, HD, KP_HD, NP_HD, HD, K2_HD, 0);
    k_mma_gemm<<<gHD, 256, GEMM_SMEM>>>(A0, B0, p_h2, HD, K2_HD, bo, 1.0f, 0, 0);

    // 8) conv4 (merged): h3 = [ln(h2)|agg] @ [Wself4;Wneigh4] + b4
    k_ln_split<<<N_TRAIN, 256>>>(p_h2, ln2g, ln2b, A0, HD, KP_HD, K2_C4);
    k_split_a3<<<cdiv(spHD, 256), 256>>>(p_agg, A0, N_TRAIN, SRC, KP_HD, SRC, K2_C4, 3 * KP_HD);
    k_split_bt3<<<dim3(KP_HD / 32, NP_HD / 32), tb>>>(Wself4, B0, HD, OUTD, KP_HD, NP_HD, OUTD, K2_C4, 0);
    k_split_bt3<<<dim3(KP_HD / 32, NP_HD / 32), tb>>>(Wneigh4, B0, SRC, OUTD, KP_HD, NP_HD, OUTD, K2_C4, 3 * KP_HD);
    k_mma_gemm<<<gHD, 256, GEMM_SMEM>>>(A0, B0, p_h3, OUTD, K2_C4, b4, 1.0f, 0, 0);

    // 9) BN4 + leaky -> x_hat (fp32) AND A-split for lin2
    k_bn_partial<<<dim3(cdiv(OUTD, 256), 32), 256>>>(p_h3, OUTD);
    k_bn_final<<<cdiv(OUTD, 256), 256>>>(bn4g, bn4b, OUTD);
    k_bn_split_out<<<cdiv(bnHD, 256), 256>>>(p_h3, out_xhat, A0, OUTD, KP_HD, K2_HD);

    // 10) head: t = relu(x_hat @ Wlin2 + blin2) ; y = t @ Wce + bce
    k_split_bt3<<<dim3(KP_HD / 32, NP_HD / 32), tb>>>(Wlin2, B0, OUTD, OUTD, KP_HD, NP_HD, OUTD, K2_HD, 0);
    k_mma_gemm<<<gHD, 256, GEMM_SMEM>>>(A0, B0, p_t, OUTD, K2_HD, blin2, 1.0f, 0, 1);
    k_out_gemm<<<N_TRAIN, 256>>>(p_t, Wce, bce, out_y);
}